// round 2
// baseline (speedup 1.0000x reference)
#include <cuda_runtime.h>

#define TOK   16384
#define KCB   8192
#define CDIM  256
#define BM    64
#define BN    64

#define ZS_STRIDE  257
#define CBS_STRIDE 68
#define SMEM_BYTES ((BM*ZS_STRIDE + 32*CBS_STRIDE) * 4)

// scratch (device globals: no allocation allowed in kernel_launch)
__device__ float g_zflat[TOK * CDIM];
__device__ float g_zsq[TOK];
__device__ float g_esq[KCB];
__device__ int   g_codes[TOK];
__device__ float g_tokloss[TOK];

// ---------------------------------------------------------------------------
// 1) transpose z (B,C,H,W) -> z_flat (t = b*1024 + h*32 + w, c)
// ---------------------------------------------------------------------------
__global__ void k_transpose(const float* __restrict__ z) {
    __shared__ float tile[32][33];
    int b  = blockIdx.z;
    int c0 = blockIdx.y << 5;
    int p0 = blockIdx.x << 5;   // hw tile
    int tx = threadIdx.x, ty = threadIdx.y;
    // read z[b, c0+ty, p0+tx]  (coalesced along hw)
    tile[ty][tx] = z[((b * CDIM + c0 + ty) << 10) + p0 + tx];
    __syncthreads();
    // write z_flat[b*1024 + p0 + ty][c0 + tx]  (coalesced along c)
    g_zflat[(b * 1024 + p0 + ty) * CDIM + c0 + tx] = tile[tx][ty];
}

// ---------------------------------------------------------------------------
// 2) z_sq[t] = sum_c z^2     (one warp per token)
// ---------------------------------------------------------------------------
__global__ void k_zsq() {
    int t    = blockIdx.x * 8 + threadIdx.y;
    int lane = threadIdx.x;
    float s = 0.f;
#pragma unroll
    for (int i = 0; i < 8; i++) {
        float v = g_zflat[t * CDIM + lane + i * 32];
        s += v * v;
    }
#pragma unroll
    for (int off = 16; off; off >>= 1) s += __shfl_down_sync(0xffffffffu, s, off);
    if (lane == 0) g_zsq[t] = s;
}

// ---------------------------------------------------------------------------
// 3) e_sq[k] = sum_c e^2
// ---------------------------------------------------------------------------
__global__ void k_esq(const float* __restrict__ cb) {
    int k    = blockIdx.x * 8 + threadIdx.y;
    int lane = threadIdx.x;
    float s = 0.f;
#pragma unroll
    for (int i = 0; i < 8; i++) {
        float v = cb[k * CDIM + lane + i * 32];
        s += v * v;
    }
#pragma unroll
    for (int off = 16; off; off >>= 1) s += __shfl_down_sync(0xffffffffu, s, off);
    if (lane == 0) g_esq[k] = s;
}

// ---------------------------------------------------------------------------
// 4) fused GEMM + argmin.
//    Block: 64 tokens.  256 threads (16x16), 4x4 register tile.
//    z tile (64x256) resident in smem; codebook streamed in 64x32 chunks,
//    transposed into smem as cbs[c][k] (pad 68) for conflict-free float4 reads.
//    dist = fl(fl(z_sq - 2*cross) + e_sq)  (matches reference elementwise math)
// ---------------------------------------------------------------------------
__global__ void __launch_bounds__(256, 2) k_argmin(const float* __restrict__ cb,
                                                   float* __restrict__ out) {
    extern __shared__ float sm[];
    float* zs  = sm;                      // 64 * 257
    float* cbs = sm + BM * ZS_STRIDE;     // 32 * 68

    int t0  = blockIdx.x * BM;
    int tid = threadIdx.x;
    int tx  = tid & 15;
    int ty  = tid >> 4;

    // load z tile (coalesced read, conflict-free write)
    for (int i = tid; i < BM * CDIM; i += 256) {
        int tk = i >> 8;
        int c  = i & 255;
        zs[tk * ZS_STRIDE + c] = g_zflat[(t0 + tk) * CDIM + c];
    }
    __syncthreads();

    float zsq[4];
#pragma unroll
    for (int u = 0; u < 4; u++) zsq[u] = g_zsq[t0 + ty * 4 + u];

    float bestd[4];
    int   besti[4];
#pragma unroll
    for (int u = 0; u < 4; u++) { bestd[u] = 3.4e38f; besti[u] = 0; }

    for (int k0 = 0; k0 < KCB; k0 += BN) {
        float acc[4][4];
#pragma unroll
        for (int u = 0; u < 4; u++)
#pragma unroll
            for (int v = 0; v < 4; v++) acc[u][v] = 0.f;

        for (int c0 = 0; c0 < CDIM; c0 += 32) {
            // load codebook tile 64x32, store transposed cbs[c][k]
#pragma unroll
            for (int j = 0; j < 8; j++) {
                int idx = tid + j * 256;
                int kk  = idx >> 5;
                int cc  = idx & 31;
                cbs[cc * CBS_STRIDE + kk] = cb[(k0 + kk) * CDIM + c0 + cc];
            }
            __syncthreads();
#pragma unroll
            for (int c = 0; c < 32; c++) {
                float4 bv = *reinterpret_cast<const float4*>(&cbs[c * CBS_STRIDE + tx * 4]);
                float a0 = zs[(ty * 4 + 0) * ZS_STRIDE + c0 + c];
                float a1 = zs[(ty * 4 + 1) * ZS_STRIDE + c0 + c];
                float a2 = zs[(ty * 4 + 2) * ZS_STRIDE + c0 + c];
                float a3 = zs[(ty * 4 + 3) * ZS_STRIDE + c0 + c];
                acc[0][0] += a0 * bv.x; acc[0][1] += a0 * bv.y;
                acc[0][2] += a0 * bv.z; acc[0][3] += a0 * bv.w;
                acc[1][0] += a1 * bv.x; acc[1][1] += a1 * bv.y;
                acc[1][2] += a1 * bv.z; acc[1][3] += a1 * bv.w;
                acc[2][0] += a2 * bv.x; acc[2][1] += a2 * bv.y;
                acc[2][2] += a2 * bv.z; acc[2][3] += a2 * bv.w;
                acc[3][0] += a3 * bv.x; acc[3][1] += a3 * bv.y;
                acc[3][2] += a3 * bv.z; acc[3][3] += a3 * bv.w;
            }
            __syncthreads();
        }

        // epilogue: distances + running argmin (first-index tie-break)
#pragma unroll
        for (int v = 0; v < 4; v++) {
            int   k  = k0 + tx * 4 + v;
            float eq = g_esq[k];
#pragma unroll
            for (int u = 0; u < 4; u++) {
                float d = (zsq[u] - 2.0f * acc[u][v]) + eq;
                if (d < bestd[u] || (d == bestd[u] && k < besti[u])) {
                    bestd[u] = d;
                    besti[u] = k;
                }
            }
        }
    }

    // reduce across the 16 tx lanes sharing each token group
#pragma unroll
    for (int u = 0; u < 4; u++) {
        float d  = bestd[u];
        int   i_ = besti[u];
#pragma unroll
        for (int off = 8; off; off >>= 1) {
            float od = __shfl_down_sync(0xffffffffu, d, off, 16);
            int   oi = __shfl_down_sync(0xffffffffu, i_, off, 16);
            if (od < d || (od == d && oi < i_)) { d = od; i_ = oi; }
        }
        if (tx == 0) {
            int t = t0 + ty * 4 + u;
            g_codes[t] = i_;
            out[t]     = (float)i_;   // codes as float32 in output slot 0
        }
    }
}

// ---------------------------------------------------------------------------
// 5) gather quantized (write NCHW) + per-token squared error
// ---------------------------------------------------------------------------
__global__ void k_quant(const float* __restrict__ cb, float* __restrict__ out) {
    int t = blockIdx.x;
    int c = threadIdx.x;           // 256
    int code = g_codes[t];
    float q  = cb[code * CDIM + c];          // coalesced row read
    float zv = g_zflat[t * CDIM + c];        // coalesced
    int b  = t >> 10;
    int hw = t & 1023;
    out[TOK + ((b * CDIM + c) << 10) + hw] = q;   // NCHW scatter
    float dv  = q - zv;
    float dsq = dv * dv;

    __shared__ float red[256];
    red[c] = dsq;
    __syncthreads();
#pragma unroll
    for (int s = 128; s > 0; s >>= 1) {
        if (c < s) red[c] += red[c + s];
        __syncthreads();
    }
    if (c == 0) g_tokloss[t] = red[0];
}

// ---------------------------------------------------------------------------
// 6) final loss: vq_loss = (1 + 0.25) * mean((q - z)^2)
// ---------------------------------------------------------------------------
__global__ void k_loss(float* __restrict__ out) {
    __shared__ float red[1024];
    int tid = threadIdx.x;
    float s = 0.f;
    for (int i = tid; i < TOK; i += 1024) s += g_tokloss[i];
    red[tid] = s;
    __syncthreads();
#pragma unroll
    for (int st = 512; st > 0; st >>= 1) {
        if (tid < st) red[tid] += red[tid + st];
        __syncthreads();
    }
    if (tid == 0)
        out[TOK + TOK * CDIM] = 1.25f * red[0] / (float)(TOK * CDIM);
}

// ---------------------------------------------------------------------------
extern "C" void kernel_launch(void* const* d_in, const int* in_sizes, int n_in,
                              void* d_out, int out_size) {
    const float* z  = (const float*)d_in[0];
    const float* cb = (const float*)d_in[1];
    float* out = (float*)d_out;

    k_transpose<<<dim3(32, 8, 16), dim3(32, 32)>>>(z);
    k_zsq<<<TOK / 8, dim3(32, 8)>>>();
    k_esq<<<KCB / 8, dim3(32, 8)>>>(cb);

    cudaFuncSetAttribute(k_argmin, cudaFuncAttributeMaxDynamicSharedMemorySize,
                         SMEM_BYTES);
    k_argmin<<<TOK / BM, 256, SMEM_BYTES>>>(cb, out);

    k_quant<<<TOK, 256>>>(cb, out);
    k_loss<<<1, 1024>>>(out);
}